// round 6
// baseline (speedup 1.0000x reference)
#include <cuda_runtime.h>
#include <cuda_fp16.h>
#include <cstdint>

#define L_DIM   1024
#define OUT_DIM 512
#define M_TOT   16384       // B*N = 64*256
#define BM      128
#define BN      128
#define KC      32
#define NCHUNK  (L_DIM / KC)   // 32
#define THREADS 256

// ---------------- device scratch (no allocations allowed) ----------------
__device__ __align__(128) unsigned short g_w[L_DIM * OUT_DIM];  // fp16 bits, [K,N]
__device__ float g_bc[OUT_DIM];

// ---------------- smem layout (dynamic) ----------------
// bias  [0,512)
// B tile (w fp16): row stride 272B (128 fp16 = 256B + 16B pad), tile = 32*272 = 8704B
#define SM_B      1024
#define B_RSTRIDE 272
#define B_TILE    (KC * B_RSTRIDE)
#define SMEM_NEED (SM_B + 2 * B_TILE)   // 18432 bytes

__device__ __forceinline__ uint32_t smem_to_u32(const void* p) {
    uint32_t a;
    asm("{ .reg .u64 t; cvta.to.shared.u64 t, %1; cvt.u32.u64 %0, t; }" : "=r"(a) : "l"(p));
    return a;
}

#define CP_ASYNC16(dst, src) \
    asm volatile("cp.async.cg.shared.global [%0], [%1], 16;" :: "r"(dst), "l"(src) : "memory")
#define CP_COMMIT()   asm volatile("cp.async.commit_group;" ::: "memory")
#define CP_WAIT_ALL() asm volatile("cp.async.wait_group 0;" ::: "memory")

#define LDMATRIX_X4_T(r0, r1, r2, r3, addr) \
    asm volatile("ldmatrix.sync.aligned.m8n8.x4.trans.shared.b16 {%0,%1,%2,%3}, [%4];" \
        : "=r"(r0), "=r"(r1), "=r"(r2), "=r"(r3) : "r"(addr))

#define MMA_FP16(d, a, b) \
    asm volatile("mma.sync.aligned.m16n8k16.row.col.f32.f16.f16.f32 " \
        "{%0,%1,%2,%3}, {%4,%5,%6,%7}, {%8,%9}, {%0,%1,%2,%3};" \
        : "+f"((d)[0]), "+f"((d)[1]), "+f"((d)[2]), "+f"((d)[3]) \
        : "r"((a)[0]), "r"((a)[1]), "r"((a)[2]), "r"((a)[3]), "r"((b)[0]), "r"((b)[1]))

// split fp32 pair into hi fp16x2 (rounded) + lo fp16x2 (residual)
__device__ __forceinline__ void split2_f16(float f0, float f1, uint32_t& h, uint32_t& l) {
    __half2 hh = __floats2half2_rn(f0, f1);
    float2 hb = __half22float2(hh);
    __half2 ll = __floats2half2_rn(f0 - hb.x, f1 - hb.y);
    h = *reinterpret_cast<uint32_t*>(&hh);
    l = *reinterpret_cast<uint32_t*>(&ll);
}

// ---------------- prep: fold 3 linears -> fp16 ----
__global__ void prep_weights(const float* __restrict__ W_in, const float* __restrict__ b_in,
                             const float* __restrict__ W_out, const float* __restrict__ b_out,
                             const float* __restrict__ W_root, const float* __restrict__ b_root) {
    int i = blockIdx.x * blockDim.x + threadIdx.x;
    if (i < L_DIM * OUT_DIM) {
        float wc = 0.5f * W_out[i] + 0.5f * W_in[i] + W_root[i];
        g_w[i] = __half_as_ushort(__float2half_rn(wc));
    }
    if (i < OUT_DIM) {
        g_bc[i] = 0.5f * b_out[i] + 0.5f * b_in[i] + b_root[i];
    }
}

// ---------------- GEMM: 128x128 CTA, A direct-from-gmem, B smem ----------
__global__ __launch_bounds__(THREADS, 2)
void gemm_hmma(const float* __restrict__ x, float* __restrict__ y) {
    extern __shared__ char smem[];
    const uint32_t sb = smem_to_u32(smem);
    float* sbias = (float*)smem;

    const int tid  = threadIdx.x;
    const int wid  = tid >> 5;
    const int lane = tid & 31;
    const int m0 = blockIdx.y * BM;
    const int n0 = blockIdx.x * BN;
    const int m_warp = (wid >> 1) * 32;     // 0,32,64,96
    const int n_warp = (wid & 1) * 64;      // 0,64

    if (tid < BN) sbias[tid] = g_bc[n0 + tid];

    float acc[2][8][4];
#pragma unroll
    for (int i = 0; i < 2; i++)
#pragma unroll
        for (int j = 0; j < 8; j++)
#pragma unroll
            for (int q = 0; q < 4; q++) acc[i][j][q] = 0.0f;

    const char* wp = (const char*)g_w;

    auto cp_b_tile = [&](int chunk, int stage) {
        const uint32_t bdst = sb + SM_B + stage * B_TILE;
        const size_t kbase = (size_t)chunk * KC;
#pragma unroll
        for (int j = 0; j < 2; j++) {
            int idx = tid + j * 256;             // 0..511 = 32 rows x 16 chunks of 16B
            int r   = idx >> 4;
            int cb  = (idx & 15) * 16;
            size_t srcoff = ((kbase + r) * OUT_DIM + n0) * 2 + cb;
            CP_ASYNC16(bdst + (uint32_t)(r * B_RSTRIDE + cb), wp + srcoff);
        }
    };

    // A fragment base pointer: this thread's (row, col-pair) within its warp's m-slice
    const float* aptr = x + (size_t)(m0 + m_warp + (lane >> 2)) * L_DIM + ((lane & 3) << 1);

    // precompute B ldmatrix base addresses (per ks added later)
    uint32_t b_ld_off[4];
#pragma unroll
    for (int p = 0; p < 4; p++)
        b_ld_off[p] = (uint32_t)((lane & 15) * B_RSTRIDE
                                 + (n_warp + p * 16 + ((lane >> 4) << 3)) * 2);

    // ---- prologue ----
    cp_b_tile(0, 0);
    CP_COMMIT();
    CP_WAIT_ALL();
    __syncthreads();

    // ---- main loop ----
    for (int i = 0; i < NCHUNK; i++) {
        const int s = i & 1;
        const int o = s ^ 1;

        if (i + 1 < NCHUNK) {
            cp_b_tile(i + 1, o);
            CP_COMMIT();
        }

        // ---- A fragments: direct LDG from gmem (L2-resident), split in regs ----
        uint32_t afh[2][2][4], afl[2][2][4];     // [mi][ks][4]
        const float* ap = aptr + (size_t)i * KC;
#pragma unroll
        for (int mi = 0; mi < 2; mi++) {
#pragma unroll
            for (int ks = 0; ks < 2; ks++) {
                const float* f = ap + (size_t)(mi * 16) * L_DIM + ks * 16;
                float2 v0 = *(const float2*)(f);
                float2 v1 = *(const float2*)(f + 8 * L_DIM);
                float2 v2 = *(const float2*)(f + 8);
                float2 v3 = *(const float2*)(f + 8 * L_DIM + 8);
                split2_f16(v0.x, v0.y, afh[mi][ks][0], afl[mi][ks][0]);
                split2_f16(v1.x, v1.y, afh[mi][ks][1], afl[mi][ks][1]);
                split2_f16(v2.x, v2.y, afh[mi][ks][2], afl[mi][ks][2]);
                split2_f16(v3.x, v3.y, afh[mi][ks][3], afl[mi][ks][3]);
            }
        }

        // ---- B frags + MMAs ----
        const uint32_t bbase = sb + SM_B + s * B_TILE;
#pragma unroll
        for (int ks = 0; ks < 2; ks++) {
            uint32_t bf[8][2];
#pragma unroll
            for (int p = 0; p < 4; p++) {
                uint32_t addr = bbase + (uint32_t)(ks * 16 * B_RSTRIDE) + b_ld_off[p];
                LDMATRIX_X4_T(bf[p * 2][0], bf[p * 2][1], bf[p * 2 + 1][0], bf[p * 2 + 1][1], addr);
            }
#pragma unroll
            for (int mi = 0; mi < 2; mi++)
#pragma unroll
                for (int nj = 0; nj < 8; nj++)
                    MMA_FP16(acc[mi][nj], afh[mi][ks], bf[nj]);
#pragma unroll
            for (int mi = 0; mi < 2; mi++)
#pragma unroll
                for (int nj = 0; nj < 8; nj++)
                    MMA_FP16(acc[mi][nj], afl[mi][ks], bf[nj]);
        }

        CP_WAIT_ALL();
        __syncthreads();
    }

    // ---- epilogue: bias add + store ----
#pragma unroll
    for (int mi = 0; mi < 2; mi++) {
        int r0 = m0 + m_warp + mi * 16 + (lane >> 2);
#pragma unroll
        for (int nj = 0; nj < 8; nj++) {
            int cl = n_warp + nj * 8 + (lane & 3) * 2;
            float b0 = sbias[cl], b1 = sbias[cl + 1];
            float2 v0 = make_float2(acc[mi][nj][0] + b0, acc[mi][nj][1] + b1);
            float2 v1 = make_float2(acc[mi][nj][2] + b0, acc[mi][nj][3] + b1);
            *(float2*)(y + (size_t)r0 * OUT_DIM + n0 + cl) = v0;
            *(float2*)(y + (size_t)(r0 + 8) * OUT_DIM + n0 + cl) = v1;
        }
    }
}

// ---------------- launch ----------------
extern "C" void kernel_launch(void* const* d_in, const int* in_sizes, int n_in,
                              void* d_out, int out_size) {
    // metadata order: x, At, W_in, b_in, W_out, b_out, W_root, b_root
    const float* x      = (const float*)d_in[0];
    // d_in[1] = At — mathematically dead (ChebConv K=1: no neighbor aggregation)
    const float* W_in   = (const float*)d_in[2];
    const float* b_in   = (const float*)d_in[3];
    const float* W_out  = (const float*)d_in[4];
    const float* b_out  = (const float*)d_in[5];
    const float* W_root = (const float*)d_in[6];
    const float* b_root = (const float*)d_in[7];
    float* y = (float*)d_out;

    prep_weights<<<(L_DIM * OUT_DIM + 255) / 256, 256>>>(W_in, b_in, W_out, b_out, W_root, b_root);

    cudaFuncSetAttribute(gemm_hmma, cudaFuncAttributeMaxDynamicSharedMemorySize, SMEM_NEED);
    gemm_hmma<<<dim3(OUT_DIM / BN, M_TOT / BM), THREADS, SMEM_NEED>>>(x, y);
}